// round 2
// baseline (speedup 1.0000x reference)
#include <cuda_runtime.h>
#include <cuda_bf16.h>

#define NUM_USER  8192
#define NUM_ITEM  16384
#define NUM_HIDDEN 64
#define NNZ       200000

#define BM 128
#define BN 128
#define BK 32
#define SPAD 132   // smem row stride (floats): multiple of 4 for LDS.128 alignment

__device__ unsigned char g_user_mask[NUM_USER];
__device__ unsigned char g_item_mask[NUM_ITEM];
__device__ int g_idx_is64;

// ---------------------------------------------------------------------------
// Kernel 1: clear masks + detect index dtype (int32 vs int64).
// Values are in [0, 8192), so an int64 buffer viewed as int32 has every odd
// word == 0. Probability of a false positive on genuine int32 data over 64
// samples is (1/8192)^64 ~ 0. Deterministic for fixed inputs.
// ---------------------------------------------------------------------------
__global__ void clear_masks(const int* __restrict__ idx32) {
    int t = blockIdx.x * blockDim.x + threadIdx.x;
    if (t == 0) {
        int all0 = 1;
#pragma unroll
        for (int k = 0; k < 64; ++k) all0 &= (idx32[2 * k + 1] == 0);
        g_idx_is64 = all0;
    }
    int* um = (int*)g_user_mask;
    int* im = (int*)g_item_mask;
    if (t < NUM_USER / 4) um[t] = 0;
    if (t < NUM_ITEM / 4) im[t] = 0;
}

__device__ __forceinline__ void load_pair(const void* idxv, int t, int& u, int& i) {
    if (g_idx_is64) {
        const long long* p = (const long long*)idxv;
        u = (int)p[t];
        i = (int)p[NNZ + t];
    } else {
        const int* p = (const int*)idxv;
        u = p[t];
        i = p[NNZ + t];
    }
}

// ---------------------------------------------------------------------------
// Kernel 2: set row masks from the index list.
// ---------------------------------------------------------------------------
__global__ void set_masks(const void* __restrict__ idxv) {
    int t = blockIdx.x * blockDim.x + threadIdx.x;
    if (t >= NNZ) return;
    int u, i;
    load_pair(idxv, t, u, i);
    g_user_mask[u] = 1;
    g_item_mask[i] = 1;
}

// ---------------------------------------------------------------------------
// Kernel 3: masked GEMM  pred[u,i] = sum_h eu[u,h]*um[u] * ei[i,h]*im[i]
// 128x128 tile per block, 256 threads, 8x8 register micro-tile, BK=32.
// Tiles where the whole item (or user) slab is masked out degenerate to a
// vectorized zero-store (half of all tiles for this data distribution).
// ---------------------------------------------------------------------------
__global__ void __launch_bounds__(256)
mf_gemm(const float* __restrict__ eu, const float* __restrict__ ei,
        float* __restrict__ pred) {
    __shared__ float As[BK][SPAD];   // [h][m]
    __shared__ float Bs[BK][SPAD];   // [h][n]

    const int t    = threadIdx.x;
    const int row0 = blockIdx.y * BM;
    const int col0 = blockIdx.x * BN;

    // Whole-tile mask check (block-uniform branch).
    int has_item = __syncthreads_or(t < BN ? (int)g_item_mask[col0 + t] : 0);
    int has_user = __syncthreads_or(t < BM ? (int)g_user_mask[row0 + t] : 0);

    float* out = pred + (size_t)row0 * NUM_ITEM + col0;

    if (!has_item || !has_user) {
        // Pure zero-store: 128x128 floats = 4096 float4, 8 warps x 16 rows.
        const float4 z = make_float4(0.f, 0.f, 0.f, 0.f);
        const int warp = t >> 5, lane = t & 31;
        for (int r = warp; r < BM; r += 8)
            ((float4*)(out + (size_t)r * NUM_ITEM))[lane] = z;
        return;
    }

    float acc[8][8];
#pragma unroll
    for (int i = 0; i < 8; ++i)
#pragma unroll
        for (int j = 0; j < 8; ++j) acc[i][j] = 0.f;

    const int tm = t >> 4;         // 0..15
    const int tn = t & 15;         // 0..15
    const int lr = t >> 3;         // 0..31  (row group for loads)
    const int lc = (t & 7) * 4;    // 0..28  (h offset for loads)

#pragma unroll 1
    for (int kk = 0; kk < NUM_HIDDEN; kk += BK) {
        __syncthreads();
        // Load 128 rows x 32 h of A and B, transposed into smem, masked.
#pragma unroll
        for (int r = 0; r < 4; ++r) {
            const int m = lr + 32 * r;
            float4 va = *(const float4*)(eu + (size_t)(row0 + m) * NUM_HIDDEN + kk + lc);
            float um = (float)g_user_mask[row0 + m];
            As[lc + 0][m] = va.x * um;
            As[lc + 1][m] = va.y * um;
            As[lc + 2][m] = va.z * um;
            As[lc + 3][m] = va.w * um;

            float4 vb = *(const float4*)(ei + (size_t)(col0 + m) * NUM_HIDDEN + kk + lc);
            float im = (float)g_item_mask[col0 + m];
            Bs[lc + 0][m] = vb.x * im;
            Bs[lc + 1][m] = vb.y * im;
            Bs[lc + 2][m] = vb.z * im;
            Bs[lc + 3][m] = vb.w * im;
        }
        __syncthreads();

#pragma unroll 8
        for (int h = 0; h < BK; ++h) {
            float a[8], b[8];
            float4 a0 = *(const float4*)&As[h][tm * 8];
            float4 a1 = *(const float4*)&As[h][tm * 8 + 4];
            float4 b0 = *(const float4*)&Bs[h][tn * 8];
            float4 b1 = *(const float4*)&Bs[h][tn * 8 + 4];
            a[0] = a0.x; a[1] = a0.y; a[2] = a0.z; a[3] = a0.w;
            a[4] = a1.x; a[5] = a1.y; a[6] = a1.z; a[7] = a1.w;
            b[0] = b0.x; b[1] = b0.y; b[2] = b0.z; b[3] = b0.w;
            b[4] = b1.x; b[5] = b1.y; b[6] = b1.z; b[7] = b1.w;
#pragma unroll
            for (int i = 0; i < 8; ++i)
#pragma unroll
                for (int j = 0; j < 8; ++j)
                    acc[i][j] += a[i] * b[j];
        }
    }

    // Writeback: 8 rows x 8 cols per thread, two float4 per row.
#pragma unroll
    for (int i = 0; i < 8; ++i) {
        float* p = out + (size_t)(tm * 8 + i) * NUM_ITEM + tn * 8;
        *(float4*)(p)     = make_float4(acc[i][0], acc[i][1], acc[i][2], acc[i][3]);
        *(float4*)(p + 4) = make_float4(acc[i][4], acc[i][5], acc[i][6], acc[i][7]);
    }
}

// ---------------------------------------------------------------------------
// Kernel 4: zero the label region, write the ratio scalar.
// ---------------------------------------------------------------------------
__global__ void fill_label(float* __restrict__ out) {
    const size_t n4 = (size_t)NUM_USER * NUM_ITEM / 4;
    float4* p = (float4*)(out + (size_t)NUM_USER * NUM_ITEM);
    const float4 z = make_float4(0.f, 0.f, 0.f, 0.f);
    size_t stride = (size_t)gridDim.x * blockDim.x;
    for (size_t k = (size_t)blockIdx.x * blockDim.x + threadIdx.x; k < n4; k += stride)
        p[k] = z;
    if (blockIdx.x == 0 && threadIdx.x == 0)
        out[(size_t)2 * NUM_USER * NUM_ITEM] =
            (float)((double)NUM_USER * (double)NUM_ITEM / (double)NNZ);
}

// ---------------------------------------------------------------------------
// Kernel 5: scatter-add ratings into label (duplicates accumulate).
// ---------------------------------------------------------------------------
__global__ void scatter_label(const void* __restrict__ idxv,
                              const float* __restrict__ ratings,
                              float* __restrict__ out) {
    int t = blockIdx.x * blockDim.x + threadIdx.x;
    if (t >= NNZ) return;
    int u, i;
    load_pair(idxv, t, u, i);
    atomicAdd(out + (size_t)NUM_USER * NUM_ITEM + (size_t)u * NUM_ITEM + i,
              ratings[t]);
}

extern "C" void kernel_launch(void* const* d_in, const int* in_sizes, int n_in,
                              void* d_out, int out_size) {
    const float* eu      = (const float*)d_in[0];
    const float* ei      = (const float*)d_in[1];
    const void*  idx     = d_in[2];
    const float* ratings = (const float*)d_in[3];
    float* out = (float*)d_out;

    clear_masks<<<16, 256>>>((const int*)idx);
    set_masks<<<(NNZ + 255) / 256, 256>>>(idx);
    fill_label<<<16384, 256>>>(out);
    dim3 grid(NUM_ITEM / BN, NUM_USER / BM);
    mf_gemm<<<grid, 256>>>(eu, ei, out);
    scatter_label<<<(NNZ + 255) / 256, 256>>>(idx, ratings, out);
}

// round 4
// speedup vs baseline: 1.6019x; 1.6019x over previous
#include <cuda_runtime.h>
#include <cuda_bf16.h>
#include <cstdint>

#define NUM_USER  8192
#define NUM_ITEM  16384
#define NUM_HIDDEN 64
#define NNZ       200000

#define BM 128
#define BN 128
#define KPAD 68   // smem row stride in words: frag LDS conflict-free, 16B aligned

__device__ unsigned char g_user_mask[NUM_USER];
__device__ unsigned char g_item_mask[NUM_ITEM];
__device__ int g_idx_is64;

// ---------------------------------------------------------------------------
// tf32 helpers
// ---------------------------------------------------------------------------
__device__ __forceinline__ uint32_t tf32_of(float x) {
    uint32_t r; asm("cvt.rna.tf32.f32 %0, %1;" : "=r"(r) : "f"(x)); return r;
}

__device__ __forceinline__ void mma_tf32(float* c, const uint32_t* a, const uint32_t* b) {
    asm("mma.sync.aligned.m16n8k8.row.col.f32.tf32.tf32.f32 "
        "{%0,%1,%2,%3}, {%4,%5,%6,%7}, {%8,%9}, {%0,%1,%2,%3};"
        : "+f"(c[0]), "+f"(c[1]), "+f"(c[2]), "+f"(c[3])
        : "r"(a[0]), "r"(a[1]), "r"(a[2]), "r"(a[3]), "r"(b[0]), "r"(b[1]));
}

// ---------------------------------------------------------------------------
// Kernel 1: clear masks, detect index dtype (int32 vs int64), write ratio.
// ---------------------------------------------------------------------------
__global__ void clear_masks(const int* __restrict__ idx32, float* __restrict__ out) {
    int t = blockIdx.x * blockDim.x + threadIdx.x;
    if (t == 0) {
        int all0 = 1;
#pragma unroll
        for (int k = 0; k < 64; ++k) all0 &= (idx32[2 * k + 1] == 0);
        g_idx_is64 = all0;
        out[(size_t)2 * NUM_USER * NUM_ITEM] =
            (float)((double)NUM_USER * (double)NUM_ITEM / (double)NNZ);
    }
    int* um = (int*)g_user_mask;
    int* im = (int*)g_item_mask;
    if (t < NUM_USER / 4) um[t] = 0;
    if (t < NUM_ITEM / 4) im[t] = 0;
}

__device__ __forceinline__ void load_pair(const void* idxv, int t, int& u, int& i) {
    if (g_idx_is64) {
        const long long* p = (const long long*)idxv;
        u = (int)p[t];
        i = (int)p[NNZ + t];
    } else {
        const int* p = (const int*)idxv;
        u = p[t];
        i = p[NNZ + t];
    }
}

__global__ void set_masks(const void* __restrict__ idxv) {
    int t = blockIdx.x * blockDim.x + threadIdx.x;
    if (t >= NNZ) return;
    int u, i;
    load_pair(idxv, t, u, i);
    g_user_mask[u] = 1;
    g_item_mask[i] = 1;
}

// ---------------------------------------------------------------------------
// Zero a 128x128 tile: each of 8 warps streams rows, 512B/row per warp op.
// ---------------------------------------------------------------------------
__device__ __forceinline__ void zero_tile(float* base, int t) {
    const float4 z = make_float4(0.f, 0.f, 0.f, 0.f);
    const int warp = t >> 5, lane = t & 31;
#pragma unroll
    for (int r = warp; r < BM; r += 8)
        ((float4*)(base + (size_t)r * NUM_ITEM))[lane] = z;
}

// ---------------------------------------------------------------------------
// Kernel 3: fused masked tf32-MMA GEMM + label-tile zeroing.
// 128x128 tile, 256 threads = 8 warps (2x4), warp tile 64x32,
// m16n8k8 atoms: 4 m-atoms x 4 n-atoms x 8 k-steps. Whole K=64 staged once.
// ---------------------------------------------------------------------------
__global__ void __launch_bounds__(256)
mf_gemm(const float* __restrict__ eu, const float* __restrict__ ei,
        float* __restrict__ out) {
    __shared__ uint32_t As[BM * KPAD];
    __shared__ uint32_t Bs[BN * KPAD];

    const int t    = threadIdx.x;
    const int row0 = blockIdx.y * BM;
    const int col0 = blockIdx.x * BN;

    int has_item = __syncthreads_or(t < BN ? (int)g_item_mask[col0 + t] : 0);
    int has_user = __syncthreads_or(t < BM ? (int)g_user_mask[row0 + t] : 0);

    float* pred  = out + (size_t)row0 * NUM_ITEM + col0;
    float* label = pred + (size_t)NUM_USER * NUM_ITEM;

    if (!has_item || !has_user) {
        zero_tile(pred, t);
        zero_tile(label, t);
        return;
    }

    // Stage A and B (masked, tf32-converted) into smem. 4 threads/row,
    // each thread: 4 float4 per row, 2 rows per matrix.
    {
        const int rsub = t >> 2;   // 0..63
        const int f4   = t & 3;
#pragma unroll
        for (int pass = 0; pass < 2; ++pass) {
            const int m = rsub + 64 * pass;
            const float4* arow = (const float4*)(eu + (size_t)(row0 + m) * NUM_HIDDEN);
            const float4* brow = (const float4*)(ei + (size_t)(col0 + m) * NUM_HIDDEN);
            const float um = (float)g_user_mask[row0 + m];
            const float im = (float)g_item_mask[col0 + m];
#pragma unroll
            for (int q = 0; q < 4; ++q) {
                const int kf = f4 + 4 * q;          // float4 slot 0..15
                float4 va = arow[kf];
                uint4 ta = make_uint4(tf32_of(va.x * um), tf32_of(va.y * um),
                                      tf32_of(va.z * um), tf32_of(va.w * um));
                *(uint4*)&As[m * KPAD + kf * 4] = ta;
                float4 vb = brow[kf];
                uint4 tb = make_uint4(tf32_of(vb.x * im), tf32_of(vb.y * im),
                                      tf32_of(vb.z * im), tf32_of(vb.w * im));
                *(uint4*)&Bs[m * KPAD + kf * 4] = tb;
            }
        }
    }
    __syncthreads();

    const int lane = t & 31, warp = t >> 5;
    const int wm = warp >> 2;          // 0..1  -> 64 rows
    const int wn = warp & 3;           // 0..3  -> 32 cols
    const int lr = lane >> 2;          // 0..7
    const int lc = lane & 3;           // 0..3

    float acc[4][4][4];
#pragma unroll
    for (int ma = 0; ma < 4; ++ma)
#pragma unroll
        for (int na = 0; na < 4; ++na)
#pragma unroll
            for (int j = 0; j < 4; ++j) acc[ma][na][j] = 0.f;

    const uint32_t* Abase = As + (wm * 64 + lr) * KPAD + lc;
    const uint32_t* Bbase = Bs + (wn * 32 + lr) * KPAD + lc;

#pragma unroll
    for (int ks = 0; ks < 8; ++ks) {
        uint32_t a[4][4], b[4][2];
#pragma unroll
        for (int ma = 0; ma < 4; ++ma) {
            const uint32_t* p = Abase + ma * 16 * KPAD + ks * 8;
            a[ma][0] = p[0];
            a[ma][1] = p[8 * KPAD];
            a[ma][2] = p[4];
            a[ma][3] = p[8 * KPAD + 4];
        }
#pragma unroll
        for (int na = 0; na < 4; ++na) {
            const uint32_t* p = Bbase + na * 8 * KPAD + ks * 8;
            b[na][0] = p[0];
            b[na][1] = p[4];
        }
#pragma unroll
        for (int ma = 0; ma < 4; ++ma)
#pragma unroll
            for (int na = 0; na < 4; ++na)
                mma_tf32(acc[ma][na], a[ma], b[na]);
    }

    // Writeback pred tile: per atom, thread owns (row, 2 cols) and (row+8, 2 cols).
#pragma unroll
    for (int ma = 0; ma < 4; ++ma) {
        const int r = wm * 64 + ma * 16 + lr;
#pragma unroll
        for (int na = 0; na < 4; ++na) {
            const int c = wn * 32 + na * 8 + 2 * lc;
            *(float2*)(pred + (size_t)r * NUM_ITEM + c) =
                make_float2(acc[ma][na][0], acc[ma][na][1]);
            *(float2*)(pred + (size_t)(r + 8) * NUM_ITEM + c) =
                make_float2(acc[ma][na][2], acc[ma][na][3]);
        }
    }

    // Fused: zero the matching label tile.
    zero_tile(label, t);
}

// ---------------------------------------------------------------------------
// Kernel 4: scatter-add ratings into label (duplicates accumulate).
// ---------------------------------------------------------------------------
__global__ void scatter_label(const void* __restrict__ idxv,
                              const float* __restrict__ ratings,
                              float* __restrict__ out) {
    int t = blockIdx.x * blockDim.x + threadIdx.x;
    if (t >= NNZ) return;
    int u, i;
    load_pair(idxv, t, u, i);
    atomicAdd(out + (size_t)NUM_USER * NUM_ITEM + (size_t)u * NUM_ITEM + i,
              ratings[t]);
}

extern "C" void kernel_launch(void* const* d_in, const int* in_sizes, int n_in,
                              void* d_out, int out_size) {
    const float* eu      = (const float*)d_in[0];
    const float* ei      = (const float*)d_in[1];
    const void*  idx     = d_in[2];
    const float* ratings = (const float*)d_in[3];
    float* out = (float*)d_out;

    clear_masks<<<16, 256>>>((const int*)idx, out);
    set_masks<<<(NNZ + 255) / 256, 256>>>(idx);
    dim3 grid(NUM_ITEM / BN, NUM_USER / BM);
    mf_gemm<<<grid, 256>>>(eu, ei, out);
    scatter_label<<<(NNZ + 255) / 256, 256>>>(idx, ratings, out);
}

// round 5
// speedup vs baseline: 1.6837x; 1.0511x over previous
#include <cuda_runtime.h>
#include <cuda_bf16.h>
#include <cstdint>

#define NUM_USER  8192
#define NUM_ITEM  16384
#define NUM_HIDDEN 64
#define NNZ       200000

#define BM 128
#define BN 128
#define KPAD 68   // smem row stride in words: all ldmatrix phases conflict-free

__device__ unsigned char g_user_mask[NUM_USER];
__device__ unsigned char g_item_mask[NUM_ITEM];
__device__ int g_idx_is64;

// ---------------------------------------------------------------------------
// tf32 / mma / ldmatrix helpers
// ---------------------------------------------------------------------------
__device__ __forceinline__ uint32_t tf32_of(float x) {
    uint32_t r; asm("cvt.rna.tf32.f32 %0, %1;" : "=r"(r) : "f"(x)); return r;
}

__device__ __forceinline__ void mma_tf32(float* c, const uint32_t* a, const uint32_t* b) {
    asm("mma.sync.aligned.m16n8k8.row.col.f32.tf32.tf32.f32 "
        "{%0,%1,%2,%3}, {%4,%5,%6,%7}, {%8,%9}, {%0,%1,%2,%3};"
        : "+f"(c[0]), "+f"(c[1]), "+f"(c[2]), "+f"(c[3])
        : "r"(a[0]), "r"(a[1]), "r"(a[2]), "r"(a[3]), "r"(b[0]), "r"(b[1]));
}

__device__ __forceinline__ void ldsm_x4(uint32_t* r, uint32_t saddr) {
    asm volatile("ldmatrix.sync.aligned.m8n8.x4.shared.b16 {%0,%1,%2,%3}, [%4];"
        : "=r"(r[0]), "=r"(r[1]), "=r"(r[2]), "=r"(r[3]) : "r"(saddr));
}

__device__ __forceinline__ void ldsm_x2(uint32_t* r, uint32_t saddr) {
    asm volatile("ldmatrix.sync.aligned.m8n8.x2.shared.b16 {%0,%1}, [%2];"
        : "=r"(r[0]), "=r"(r[1]) : "r"(saddr));
}

// ---------------------------------------------------------------------------
// Kernel 1: clear masks, detect index dtype (int32 vs int64), write ratio.
// Values are in [0, 8192): an int64 buffer viewed as int32 has every odd
// word == 0 over 64 samples -> deterministic dtype detection.
// ---------------------------------------------------------------------------
__global__ void clear_masks(const int* __restrict__ idx32, float* __restrict__ out) {
    int t = blockIdx.x * blockDim.x + threadIdx.x;
    if (t == 0) {
        int all0 = 1;
#pragma unroll
        for (int k = 0; k < 64; ++k) all0 &= (idx32[2 * k + 1] == 0);
        g_idx_is64 = all0;
        out[(size_t)2 * NUM_USER * NUM_ITEM] =
            (float)((double)NUM_USER * (double)NUM_ITEM / (double)NNZ);
    }
    int* um = (int*)g_user_mask;
    int* im = (int*)g_item_mask;
    if (t < NUM_USER / 4) um[t] = 0;
    if (t < NUM_ITEM / 4) im[t] = 0;
}

__device__ __forceinline__ void load_pair(const void* idxv, int t, int& u, int& i) {
    if (g_idx_is64) {
        const long long* p = (const long long*)idxv;
        u = (int)p[t];
        i = (int)p[NNZ + t];
    } else {
        const int* p = (const int*)idxv;
        u = p[t];
        i = p[NNZ + t];
    }
}

__global__ void set_masks(const void* __restrict__ idxv) {
    int t = blockIdx.x * blockDim.x + threadIdx.x;
    if (t >= NNZ) return;
    int u, i;
    load_pair(idxv, t, u, i);
    g_user_mask[u] = 1;
    g_item_mask[i] = 1;
}

// ---------------------------------------------------------------------------
// Zero a 128x128 tile: 8 warps stream rows, 512B contiguous per warp op.
// ---------------------------------------------------------------------------
__device__ __forceinline__ void zero_tile(float* base, int t) {
    const float4 z = make_float4(0.f, 0.f, 0.f, 0.f);
    const int warp = t >> 5, lane = t & 31;
#pragma unroll
    for (int r = warp; r < BM; r += 8)
        ((float4*)(base + (size_t)r * NUM_ITEM))[lane] = z;
}

// ---------------------------------------------------------------------------
// Kernel 3: fused masked tf32-MMA GEMM + label-tile zeroing.
// 128x128 tile, 8 warps (2x4), warp tile 64x32, m16n8k8 atoms.
// Fragments fetched via ldmatrix (x4 for A, x2 for B).
// ---------------------------------------------------------------------------
__global__ void __launch_bounds__(256)
mf_gemm(const float* __restrict__ eu, const float* __restrict__ ei,
        float* __restrict__ out) {
    __shared__ uint32_t As[BM * KPAD];
    __shared__ uint32_t Bs[BN * KPAD];

    const int t    = threadIdx.x;
    const int row0 = blockIdx.y * BM;
    const int col0 = blockIdx.x * BN;

    int has_item = __syncthreads_or(t < BN ? (int)g_item_mask[col0 + t] : 0);
    int has_user = __syncthreads_or(t < BM ? (int)g_user_mask[row0 + t] : 0);

    float* pred  = out + (size_t)row0 * NUM_ITEM + col0;
    float* label = pred + (size_t)NUM_USER * NUM_ITEM;

    if (!has_item || !has_user) {
        zero_tile(pred, t);
        zero_tile(label, t);
        return;
    }

    // Stage A and B (masked, tf32-converted) into smem.
    {
        const int rsub = t >> 2;   // 0..63
        const int f4   = t & 3;
#pragma unroll
        for (int pass = 0; pass < 2; ++pass) {
            const int m = rsub + 64 * pass;
            const float4* arow = (const float4*)(eu + (size_t)(row0 + m) * NUM_HIDDEN);
            const float4* brow = (const float4*)(ei + (size_t)(col0 + m) * NUM_HIDDEN);
            const float um = (float)g_user_mask[row0 + m];
            const float im = (float)g_item_mask[col0 + m];
#pragma unroll
            for (int q = 0; q < 4; ++q) {
                const int kf = f4 + 4 * q;          // float4 slot 0..15
                float4 va = arow[kf];
                uint4 ta = make_uint4(tf32_of(va.x * um), tf32_of(va.y * um),
                                      tf32_of(va.z * um), tf32_of(va.w * um));
                *(uint4*)&As[m * KPAD + kf * 4] = ta;
                float4 vb = brow[kf];
                uint4 tb = make_uint4(tf32_of(vb.x * im), tf32_of(vb.y * im),
                                      tf32_of(vb.z * im), tf32_of(vb.w * im));
                *(uint4*)&Bs[m * KPAD + kf * 4] = tb;
            }
        }
    }
    __syncthreads();

    const int lane = t & 31, warp = t >> 5;
    const int wm = warp >> 2;          // 0..1  -> 64 rows
    const int wn = warp & 3;           // 0..3  -> 32 cols
    const int lr = lane >> 2;          // 0..7
    const int lc = lane & 3;           // 0..3

    // ldmatrix per-lane source rows.
    // A (x4): matrix j from lanes 8j..8j+7; m0=rows0-7/k0-3, m1=rows8-15/k0-3,
    //         m2=rows0-7/k4-7, m3=rows8-15/k4-7  -> a0..a3 in mma order.
    const int amat = lane >> 3, ar = lane & 7;
    const int aRow = wm * 64 + (amat & 1) * 8 + ar;
    const int aKo  = (amat >> 1) * 4;
    // B (x2): lanes 0..15; m0 = n-rows/k0-3, m1 = n-rows/k4-7.
    const int bmat = (lane >> 3) & 1, br = lane & 7;
    const int bRow = wn * 32 + br;
    const int bKo  = bmat * 4;

    const uint32_t As_s = (uint32_t)__cvta_generic_to_shared(As);
    const uint32_t Bs_s = (uint32_t)__cvta_generic_to_shared(Bs);

    float acc[4][4][4];
#pragma unroll
    for (int ma = 0; ma < 4; ++ma)
#pragma unroll
        for (int na = 0; na < 4; ++na)
#pragma unroll
            for (int j = 0; j < 4; ++j) acc[ma][na][j] = 0.f;

#pragma unroll
    for (int ks = 0; ks < 8; ++ks) {
        uint32_t a[4][4], b[4][2];
#pragma unroll
        for (int ma = 0; ma < 4; ++ma)
            ldsm_x4(a[ma], As_s + (uint32_t)(((aRow + ma * 16) * KPAD) + ks * 8 + aKo) * 4u);
#pragma unroll
        for (int na = 0; na < 4; ++na)
            ldsm_x2(b[na], Bs_s + (uint32_t)(((bRow + na * 8) * KPAD) + ks * 8 + bKo) * 4u);
#pragma unroll
        for (int ma = 0; ma < 4; ++ma)
#pragma unroll
            for (int na = 0; na < 4; ++na)
                mma_tf32(acc[ma][na], a[ma], b[na]);
    }

    // Writeback pred tile: per atom, thread owns (row, 2 cols) and (row+8, 2 cols).
#pragma unroll
    for (int ma = 0; ma < 4; ++ma) {
        const int r = wm * 64 + ma * 16 + lr;
#pragma unroll
        for (int na = 0; na < 4; ++na) {
            const int c = wn * 32 + na * 8 + 2 * lc;
            *(float2*)(pred + (size_t)r * NUM_ITEM + c) =
                make_float2(acc[ma][na][0], acc[ma][na][1]);
            *(float2*)(pred + (size_t)(r + 8) * NUM_ITEM + c) =
                make_float2(acc[ma][na][2], acc[ma][na][3]);
        }
    }

    // Fused: zero the matching label tile.
    zero_tile(label, t);
}

// ---------------------------------------------------------------------------
// Kernel 4: scatter-add ratings into label (duplicates accumulate).
// ---------------------------------------------------------------------------
__global__ void scatter_label(const void* __restrict__ idxv,
                              const float* __restrict__ ratings,
                              float* __restrict__ out) {
    int t = blockIdx.x * blockDim.x + threadIdx.x;
    if (t >= NNZ) return;
    int u, i;
    load_pair(idxv, t, u, i);
    atomicAdd(out + (size_t)NUM_USER * NUM_ITEM + (size_t)u * NUM_ITEM + i,
              ratings[t]);
}

extern "C" void kernel_launch(void* const* d_in, const int* in_sizes, int n_in,
                              void* d_out, int out_size) {
    const float* eu      = (const float*)d_in[0];
    const float* ei      = (const float*)d_in[1];
    const void*  idx     = d_in[2];
    const float* ratings = (const float*)d_in[3];
    float* out = (float*)d_out;

    clear_masks<<<16, 256>>>((const int*)idx, out);
    set_masks<<<(NNZ + 255) / 256, 256>>>(idx);
    dim3 grid(NUM_ITEM / BN, NUM_USER / BM);
    mf_gemm<<<grid, 256>>>(eu, ei, out);
    scatter_label<<<(NNZ + 255) / 256, 256>>>(idx, ratings, out);
}